// round 1
// baseline (speedup 1.0000x reference)
#include <cuda_runtime.h>

#define NN 100000
#define NE 1200000
#define DD 64

// scratch (allocation-free rule: __device__ globals)
__device__ float g_neigh[NN * DD];   // 25.6 MB
__device__ float g_deg[NN];

__global__ void __launch_bounds__(256) zero_kernel() {
    int idx = blockIdx.x * 256 + threadIdx.x;
    const int n4 = NN * DD / 4;   // 1,600,000 float4
    const int d4 = NN / 4;        // 25,000 float4
    float4 z = make_float4(0.f, 0.f, 0.f, 0.f);
    if (idx < n4) {
        reinterpret_cast<float4*>(g_neigh)[idx] = z;
    } else if (idx < n4 + d4) {
        reinterpret_cast<float4*>(g_deg)[idx - n4] = z;
    }
}

// One warp handles 2 edges: 16 lanes/edge, one float4 (16B) per lane -> 64 floats.
__global__ void __launch_bounds__(256) scatter_kernel(
    const float* __restrict__ feat, const int* __restrict__ src,
    const int* __restrict__ dst, const float* __restrict__ ew,
    const float* __restrict__ em) {
    unsigned gid = blockIdx.x * 256u + threadIdx.x;
    unsigned e = gid >> 4;     // edge id
    unsigned c = gid & 15;     // float4 chunk within the 64-float row
    // grid sized exactly: NE*16 threads, no guard needed
    int s = __ldg(src + e);
    int d = __ldg(dst + e);
    float w = __ldg(ew + e) * __ldg(em + e);
    float4 v = __ldg(reinterpret_cast<const float4*>(feat) + (size_t)s * 16 + c);
    v.x *= w; v.y *= w; v.z *= w; v.w *= w;
    float* p = g_neigh + (size_t)d * DD + c * 4;
    asm volatile("red.global.add.v4.f32 [%0], {%1, %2, %3, %4};"
                 :: "l"(p), "f"(v.x), "f"(v.y), "f"(v.z), "f"(v.w) : "memory");
    if (c == 0) {
        asm volatile("red.global.add.f32 [%0], %1;"
                     :: "l"(g_deg + d), "f"(1.0f) : "memory");
    }
}

// Tile: 32 nodes x 64 outputs per block. W_self/W_neigh transposed into shared
// with XOR swizzle at float4 granularity: conflict-free compute loads,
// coalesced global reads at fill. Static smem = 32KB (W) + 16KB (A,B) = 48KB.
__global__ void __launch_bounds__(256) gemm_kernel(
    const float* __restrict__ feat,
    const float* __restrict__ Ws, const float* __restrict__ bs,
    const float* __restrict__ Wn, const float* __restrict__ bn,
    float* __restrict__ out) {
    __shared__ float sWs[DD * DD];
    __shared__ float sWn[DD * DD];
    __shared__ float sA[32 * DD];
    __shared__ float sB[32 * DD];

    int t = threadIdx.x;

    // Fill W (transposed + swizzled): element (j,k) -> sW[k*64 + ((j>>2)^(k&15))*4 + (j&3)]
    for (int i = t; i < DD * DD; i += 256) {
        int k = i & 63;          // fast index -> coalesced global read
        int j = i >> 6;
        int gs = (j >> 2) ^ (k & 15);
        int sidx = k * 64 + gs * 4 + (j & 3);
        sWs[sidx] = Ws[i];       // Ws[i] == W_self[j*64 + k]... careful: i = j*64+k
        sWn[sidx] = Wn[i];
    }

    int base = blockIdx.x * 32;  // 3125 blocks * 32 = 100000 exactly, no guards

    // Stage 32 node rows of feat and deg-normalized neigh
    for (int i = t; i < 32 * 16; i += 256) {
        int n = i >> 4, c = i & 15;
        int node = base + n;
        float4 f = __ldg(reinterpret_cast<const float4*>(feat) + (size_t)node * 16 + c);
        reinterpret_cast<float4*>(sA)[i] = f;
        float4 h = reinterpret_cast<const float4*>(g_neigh)[(size_t)node * 16 + c];
        float inv = 1.0f / fmaxf(g_deg[node], 1.0f);
        h.x *= inv; h.y *= inv; h.z *= inv; h.w *= inv;
        reinterpret_cast<float4*>(sB)[i] = h;
    }
    __syncthreads();

    int jg = t & 15;     // output col group: j0 = jg*4
    int ng = t >> 4;     // node pair group: nodes ng*2, ng*2+1
    int j0 = jg * 4;

    float4 bias;
    bias.x = __ldg(bs + j0 + 0) + __ldg(bn + j0 + 0);
    bias.y = __ldg(bs + j0 + 1) + __ldg(bn + j0 + 1);
    bias.z = __ldg(bs + j0 + 2) + __ldg(bn + j0 + 2);
    bias.w = __ldg(bs + j0 + 3) + __ldg(bn + j0 + 3);
    float4 acc0 = bias, acc1 = bias;

    const float* pA = sA + ng * 128;   // two consecutive node rows
    const float* pB = sB + ng * 128;

    #pragma unroll 16
    for (int k = 0; k < 64; k++) {
        int widx = k * 16 + (jg ^ (k & 15));   // float4 index, undoes fill swizzle
        float4 ws = reinterpret_cast<const float4*>(sWs)[widx];
        float4 wn = reinterpret_cast<const float4*>(sWn)[widx];
        float a0 = pA[k], a1 = pA[64 + k];
        float b0 = pB[k], b1 = pB[64 + k];
        acc0.x = fmaf(a0, ws.x, acc0.x); acc0.x = fmaf(b0, wn.x, acc0.x);
        acc0.y = fmaf(a0, ws.y, acc0.y); acc0.y = fmaf(b0, wn.y, acc0.y);
        acc0.z = fmaf(a0, ws.z, acc0.z); acc0.z = fmaf(b0, wn.z, acc0.z);
        acc0.w = fmaf(a0, ws.w, acc0.w); acc0.w = fmaf(b0, wn.w, acc0.w);
        acc1.x = fmaf(a1, ws.x, acc1.x); acc1.x = fmaf(b1, wn.x, acc1.x);
        acc1.y = fmaf(a1, ws.y, acc1.y); acc1.y = fmaf(b1, wn.y, acc1.y);
        acc1.z = fmaf(a1, ws.z, acc1.z); acc1.z = fmaf(b1, wn.z, acc1.z);
        acc1.w = fmaf(a1, ws.w, acc1.w); acc1.w = fmaf(b1, wn.w, acc1.w);
    }

    int n0 = base + ng * 2;
    reinterpret_cast<float4*>(out)[(size_t)n0 * 16 + jg] = acc0;
    reinterpret_cast<float4*>(out)[(size_t)(n0 + 1) * 16 + jg] = acc1;
}

extern "C" void kernel_launch(void* const* d_in, const int* in_sizes, int n_in,
                              void* d_out, int out_size) {
    const float* feat = (const float*)d_in[0];
    const int*   src  = (const int*)d_in[1];
    const int*   dst  = (const int*)d_in[2];
    const float* ew   = (const float*)d_in[3];
    const float* em   = (const float*)d_in[4];
    const float* Ws   = (const float*)d_in[5];
    const float* bs   = (const float*)d_in[6];
    const float* Wn   = (const float*)d_in[7];
    const float* bn   = (const float*)d_in[8];
    float* out = (float*)d_out;

    // zero: 1,600,000 + 25,000 float4 slots
    zero_kernel<<<6348, 256>>>();
    // scatter: NE * 16 threads / 256 = 75000 blocks (exact)
    scatter_kernel<<<75000, 256>>>(feat, src, dst, ew, em);
    // gemm: 100000 / 32 = 3125 blocks (exact)
    gemm_kernel<<<3125, 256>>>(feat, Ws, bs, Wn, bn, out);
}

// round 2
// speedup vs baseline: 1.1716x; 1.1716x over previous
#include <cuda_runtime.h>

#define NN 100000
#define NE 1200000
#define DD 64
#define NBLK 391   // ceil(NN/256)

// scratch (__device__ globals per allocation rules)
__device__ int       g_count[NN];
__device__ int       g_off[NN];
__device__ int       g_cur[NN];
__device__ long long g_edata[NE];      // packed {w_bits, src}
__device__ int       g_partial[NBLK];
__device__ int       g_pscan[NBLK];

__global__ void __launch_bounds__(256) zero_counts() {
    int i = blockIdx.x * 256 + threadIdx.x;
    if (i < NN) g_count[i] = 0;
}

__global__ void __launch_bounds__(256) hist_kernel(const int* __restrict__ dst) {
    unsigned e = blockIdx.x * 256u + threadIdx.x;
    if (e < NE) atomicAdd(&g_count[__ldg(dst + e)], 1);
}

__global__ void __launch_bounds__(256) blocksum_kernel() {
    int i = blockIdx.x * 256 + threadIdx.x;
    int v = (i < NN) ? g_count[i] : 0;
    // warp reduce
    #pragma unroll
    for (int o = 16; o > 0; o >>= 1) v += __shfl_down_sync(0xFFFFFFFFu, v, o);
    __shared__ int ws[8];
    if ((threadIdx.x & 31) == 0) ws[threadIdx.x >> 5] = v;
    __syncthreads();
    if (threadIdx.x < 8) {
        int s = ws[threadIdx.x];
        #pragma unroll
        for (int o = 4; o > 0; o >>= 1) s += __shfl_down_sync(0xFFu, s, o);
        if (threadIdx.x == 0) g_partial[blockIdx.x] = s;
    }
}

__global__ void __launch_bounds__(512) partialscan_kernel() {
    __shared__ int arr[512];
    int t = threadIdx.x;
    int v0 = (t < NBLK) ? g_partial[t] : 0;
    arr[t] = v0;
    __syncthreads();
    #pragma unroll
    for (int off = 1; off < 512; off <<= 1) {
        int v = (t >= off) ? arr[t - off] : 0;
        __syncthreads();
        arr[t] += v;
        __syncthreads();
    }
    if (t < NBLK) g_pscan[t] = arr[t] - v0;   // exclusive
}

__global__ void __launch_bounds__(256) offsets_kernel() {
    __shared__ int arr[256];
    int t = threadIdx.x;
    int i = blockIdx.x * 256 + t;
    int c = (i < NN) ? g_count[i] : 0;
    arr[t] = c;
    __syncthreads();
    #pragma unroll
    for (int off = 1; off < 256; off <<= 1) {
        int v = (t >= off) ? arr[t - off] : 0;
        __syncthreads();
        arr[t] += v;
        __syncthreads();
    }
    if (i < NN) {
        int o = g_pscan[blockIdx.x] + arr[t] - c;  // exclusive within block + base
        g_off[i] = o;
        g_cur[i] = o;
    }
}

__global__ void __launch_bounds__(256) fill_kernel(
    const int* __restrict__ src, const int* __restrict__ dst,
    const float* __restrict__ ew, const float* __restrict__ em) {
    unsigned e = blockIdx.x * 256u + threadIdx.x;
    if (e >= NE) return;
    int d = __ldg(dst + e);
    int s = __ldg(src + e);
    float w = __ldg(ew + e) * __ldg(em + e);
    int pos = atomicAdd(&g_cur[d], 1);
    g_edata[pos] = ((long long)(unsigned)__float_as_int(w) << 32) | (unsigned)s;
}

// Fused: per-node CSR gather-reduce (registers) -> shared tile -> dual GEMM.
// Block = 32 nodes, 256 threads; 8 threads per node in phase A.
__global__ void __launch_bounds__(256) fused_kernel(
    const float* __restrict__ feat,
    const float* __restrict__ Ws, const float* __restrict__ bs,
    const float* __restrict__ Wn, const float* __restrict__ bn,
    float* __restrict__ out) {
    __shared__ float sWs[DD * DD];
    __shared__ float sWn[DD * DD];
    __shared__ float sA[32 * DD];
    __shared__ float sB[32 * DD];

    int t = threadIdx.x;

    // W fill (transposed + XOR swizzle): (j,k) -> sW[k*64 + ((j>>2)^(k&15))*4 + (j&3)]
    for (int i = t; i < DD * DD; i += 256) {
        int k = i & 63;
        int j = i >> 6;
        int sidx = k * 64 + (((j >> 2) ^ (k & 15)) << 2) + (j & 3);
        sWs[sidx] = Ws[i];
        sWn[sidx] = Wn[i];
    }

    int base = blockIdx.x * 32;   // 3125 * 32 = 100000 exact

    // stage feat rows for GEMM self-term
    for (int i = t; i < 32 * 16; i += 256) {
        int n = i >> 4, c = i & 15;
        reinterpret_cast<float4*>(sA)[i] =
            __ldg(reinterpret_cast<const float4*>(feat) + (size_t)(base + n) * 16 + c);
    }

    // Phase A: gather-reduce incoming edges. 8 threads/node, each owns
    // float4 chunks l8 and 8+l8 (contiguous 128B per 8-group per load).
    {
        int nl = t >> 3;
        int l8 = t & 7;
        int node = base + nl;
        int beg = g_off[node];
        int deg = g_count[node];
        float4 a0 = make_float4(0.f, 0.f, 0.f, 0.f);
        float4 a1 = make_float4(0.f, 0.f, 0.f, 0.f);
        const float4* f4 = reinterpret_cast<const float4*>(feat);
        for (int e = beg; e < beg + deg; e++) {
            long long v = g_edata[e];
            int s = (int)(v & 0xffffffffLL);
            float w = __int_as_float((int)(v >> 32));
            float4 f0 = __ldg(f4 + (size_t)s * 16 + l8);
            float4 f1 = __ldg(f4 + (size_t)s * 16 + 8 + l8);
            a0.x = fmaf(w, f0.x, a0.x); a0.y = fmaf(w, f0.y, a0.y);
            a0.z = fmaf(w, f0.z, a0.z); a0.w = fmaf(w, f0.w, a0.w);
            a1.x = fmaf(w, f1.x, a1.x); a1.y = fmaf(w, f1.y, a1.y);
            a1.z = fmaf(w, f1.z, a1.z); a1.w = fmaf(w, f1.w, a1.w);
        }
        float inv = 1.0f / fmaxf((float)deg, 1.0f);
        a0.x *= inv; a0.y *= inv; a0.z *= inv; a0.w *= inv;
        a1.x *= inv; a1.y *= inv; a1.z *= inv; a1.w *= inv;
        reinterpret_cast<float4*>(sB)[nl * 16 + l8] = a0;
        reinterpret_cast<float4*>(sB)[nl * 16 + 8 + l8] = a1;
    }
    __syncthreads();

    // Phase B: dual GEMM. thread = 2 nodes x 4 output cols.
    int jg = t & 15;
    int ng = t >> 4;
    int j0 = jg * 4;

    float4 bias;
    bias.x = __ldg(bs + j0 + 0) + __ldg(bn + j0 + 0);
    bias.y = __ldg(bs + j0 + 1) + __ldg(bn + j0 + 1);
    bias.z = __ldg(bs + j0 + 2) + __ldg(bn + j0 + 2);
    bias.w = __ldg(bs + j0 + 3) + __ldg(bn + j0 + 3);
    float4 acc0 = bias, acc1 = bias;

    const float* pA = sA + ng * 128;
    const float* pB = sB + ng * 128;

    #pragma unroll 16
    for (int k = 0; k < 64; k++) {
        int widx = k * 16 + (jg ^ (k & 15));
        float4 ws = reinterpret_cast<const float4*>(sWs)[widx];
        float4 wn = reinterpret_cast<const float4*>(sWn)[widx];
        float a0 = pA[k], a1 = pA[64 + k];
        float b0 = pB[k], b1 = pB[64 + k];
        acc0.x = fmaf(a0, ws.x, acc0.x); acc0.x = fmaf(b0, wn.x, acc0.x);
        acc0.y = fmaf(a0, ws.y, acc0.y); acc0.y = fmaf(b0, wn.y, acc0.y);
        acc0.z = fmaf(a0, ws.z, acc0.z); acc0.z = fmaf(b0, wn.z, acc0.z);
        acc0.w = fmaf(a0, ws.w, acc0.w); acc0.w = fmaf(b0, wn.w, acc0.w);
        acc1.x = fmaf(a1, ws.x, acc1.x); acc1.x = fmaf(b1, wn.x, acc1.x);
        acc1.y = fmaf(a1, ws.y, acc1.y); acc1.y = fmaf(b1, wn.y, acc1.y);
        acc1.z = fmaf(a1, ws.z, acc1.z); acc1.z = fmaf(b1, wn.z, acc1.z);
        acc1.w = fmaf(a1, ws.w, acc1.w); acc1.w = fmaf(b1, wn.w, acc1.w);
    }

    int n0 = base + ng * 2;
    reinterpret_cast<float4*>(out)[(size_t)n0 * 16 + jg] = acc0;
    reinterpret_cast<float4*>(out)[(size_t)(n0 + 1) * 16 + jg] = acc1;
}

extern "C" void kernel_launch(void* const* d_in, const int* in_sizes, int n_in,
                              void* d_out, int out_size) {
    const float* feat = (const float*)d_in[0];
    const int*   src  = (const int*)d_in[1];
    const int*   dst  = (const int*)d_in[2];
    const float* ew   = (const float*)d_in[3];
    const float* em   = (const float*)d_in[4];
    const float* Ws   = (const float*)d_in[5];
    const float* bs   = (const float*)d_in[6];
    const float* Wn   = (const float*)d_in[7];
    const float* bn   = (const float*)d_in[8];
    float* out = (float*)d_out;

    zero_counts<<<NBLK, 256>>>();
    hist_kernel<<<4688, 256>>>(dst);          // 4688*256 >= NE
    blocksum_kernel<<<NBLK, 256>>>();
    partialscan_kernel<<<1, 512>>>();
    offsets_kernel<<<NBLK, 256>>>();
    fill_kernel<<<4688, 256>>>(src, dst, ew, em);
    fused_kernel<<<3125, 256>>>(feat, Ws, bs, Wn, bn, out);
}